// round 13
// baseline (speedup 1.0000x reference)
#include <cuda_runtime.h>
#include <cuda_bf16.h>
#include <cstdint>
#include <math.h>

// Problem dims
#define Bb 16
#define Ss 512
#define Dd 768
#define Hh 12
#define FF 3072
#define Ll 6
#define HD 64
#define BH (Bb*Hh)
#define NROWS (Bb*Ss)
#define QKVN 2304

#define SZP (Ll*Dd*Dd)
#define SZF (Ll*Dd*FF)
#define WTOT (4*SZP + 2*SZF)

// ---------------- scratch (device globals; no runtime allocation) ----------------
__device__ float g_x   [NROWS*Dd];
__device__ float g_tmp [NROWS*Dd];
__device__ float g_qkv [(size_t)NROWS*QKVN];
__device__ float g_bqkv[Ll*QKVN];

__device__ __nv_bfloat16 g_wh[WTOT];
__device__ __nv_bfloat16 g_wl[WTOT];
__device__ __nv_bfloat16 g_xh[NROWS*Dd];
__device__ __nv_bfloat16 g_xl[NROWS*Dd];
__device__ __nv_bfloat16 g_ch[NROWS*Dd];
__device__ __nv_bfloat16 g_cl[NROWS*Dd];
__device__ __nv_bfloat16 g_fh[NROWS*FF];
__device__ __nv_bfloat16 g_fl[NROWS*FF];

// ---------------- common helpers ----------------
union BF16x4 {
    __nv_bfloat16 b[4];
    uint2 u;
};

__device__ __forceinline__ void ldsm4(uint32_t* r, uint32_t addr)
{
    asm volatile("ldmatrix.sync.aligned.m8n8.x4.shared.b16 {%0,%1,%2,%3}, [%4];"
        : "=r"(r[0]), "=r"(r[1]), "=r"(r[2]), "=r"(r[3]) : "r"(addr));
}

__device__ __forceinline__ void ldsm4t(uint32_t* r, uint32_t addr)
{
    asm volatile("ldmatrix.sync.aligned.m8n8.x4.trans.shared.b16 {%0,%1,%2,%3}, [%4];"
        : "=r"(r[0]), "=r"(r[1]), "=r"(r[2]), "=r"(r[3]) : "r"(addr));
}

__device__ __forceinline__ void mma16816(float* c, const uint32_t* a, const uint32_t* b)
{
    asm volatile("mma.sync.aligned.m16n8k16.row.col.f32.bf16.bf16.f32 "
        "{%0,%1,%2,%3}, {%4,%5,%6,%7}, {%8,%9}, {%0,%1,%2,%3};"
        : "+f"(c[0]), "+f"(c[1]), "+f"(c[2]), "+f"(c[3])
        : "r"(a[0]), "r"(a[1]), "r"(a[2]), "r"(a[3]), "r"(b[0]), "r"(b[1]));
}

__device__ __forceinline__ void split_bf16(float x, __nv_bfloat16* hi, __nv_bfloat16* lo)
{
    __nv_bfloat16 h = __float2bfloat16_rn(x);
    *hi = h;
    *lo = __float2bfloat16_rn(x - __bfloat162float(h));
}

__device__ __forceinline__ void pack_split(float x, float y, uint32_t* hp, uint32_t* lp)
{
    __nv_bfloat16 hx = __float2bfloat16_rn(x);
    __nv_bfloat16 hy = __float2bfloat16_rn(y);
    __nv_bfloat16 lx = __float2bfloat16_rn(x - __bfloat162float(hx));
    __nv_bfloat16 ly = __float2bfloat16_rn(y - __bfloat162float(hy));
    *hp = ((uint32_t)__bfloat16_as_ushort(hy) << 16) | (uint32_t)__bfloat16_as_ushort(hx);
    *lp = ((uint32_t)__bfloat16_as_ushort(ly) << 16) | (uint32_t)__bfloat16_as_ushort(lx);
}

// ---------------- split: fp32 -> bf16 hi/lo (elementwise, float4) ----------------
__global__ void split_kernel(const float* __restrict__ src, __nv_bfloat16* __restrict__ hi,
                             __nv_bfloat16* __restrict__ lo, int n4)
{
    int i = blockIdx.x*blockDim.x + threadIdx.x;
    if (i < n4) {
        float4 v = ((const float4*)src)[i];
        BF16x4 h, l;
        split_bf16(v.x, &h.b[0], &l.b[0]);
        split_bf16(v.y, &h.b[1], &l.b[1]);
        split_bf16(v.z, &h.b[2], &l.b[2]);
        split_bf16(v.w, &h.b[3], &l.b[3]);
        ((uint2*)hi)[i] = h.u;
        ((uint2*)lo)[i] = l.u;
    }
}

// ---------------- pack Wq/Wk/Wv into interleaved [Ll][Dd][2304] split bf16 ----------------
__global__ void pack_qkv(const float* __restrict__ Wq, const float* __restrict__ Wk,
                         const float* __restrict__ Wv,
                         __nv_bfloat16* __restrict__ hi, __nv_bfloat16* __restrict__ lo)
{
    int i = blockIdx.x*blockDim.x + threadIdx.x;   // over Ll*Dd*(QKVN/4)
    if (i < Ll*Dd*(QKVN/4)) {
        int c4 = i % (QKVN/4);
        int rl = i / (QKVN/4);                     // rl = l*Dd + r
        int c  = c4*4;
        int sel = c / Dd;
        int sc  = c % Dd;
        const float* src = (sel == 0) ? Wq : ((sel == 1) ? Wk : Wv);
        float4 v = *(const float4*)(src + (size_t)rl*Dd + sc);
        BF16x4 h, l;
        split_bf16(v.x, &h.b[0], &l.b[0]);
        split_bf16(v.y, &h.b[1], &l.b[1]);
        split_bf16(v.z, &h.b[2], &l.b[2]);
        split_bf16(v.w, &h.b[3], &l.b[3]);
        *(uint2*)(hi + (size_t)rl*QKVN + c) = h.u;
        *(uint2*)(lo + (size_t)rl*QKVN + c) = l.u;
    }
}

__global__ void concat_bias(const float* __restrict__ bq, const float* __restrict__ bk,
                            const float* __restrict__ bv, float* __restrict__ out)
{
    int i = blockIdx.x*blockDim.x + threadIdx.x;
    if (i < Ll*QKVN) {
        int l = i / QKVN;
        int c = i % QKVN;
        float v;
        if (c < Dd) {
            v = bq[l*Dd + c];
        } else if (c < 2*Dd) {
            v = bk[l*Dd + c - Dd];
        } else {
            v = bv[l*Dd + c - 2*Dd];
        }
        out[i] = v;
    }
}

// ---------------- embedding segment-merge + pos add ----------------
__global__ void merge_kernel(const int* __restrict__ ids, const int* __restrict__ seg,
                             const float* __restrict__ emb, const float* __restrict__ pos,
                             float* __restrict__ out)
{
    int s = blockIdx.x;
    int b = blockIdx.y;
    const int* sr = seg + b*Ss;
    int lo = 0;
    int hi = Ss;
    while (lo < hi) {
        int m = (lo + hi) >> 1;
        if (sr[m] < s) lo = m + 1; else hi = m;
    }
    int st = lo;
    lo = st;
    hi = Ss;
    while (lo < hi) {
        int m = (lo + hi) >> 1;
        if (sr[m] <= s) lo = m + 1; else hi = m;
    }
    int en = lo;
    const int* idr = ids + b*Ss;
    for (int d = threadIdx.x; d < Dd; d += blockDim.x) {
        float a;
        if (st == en) {
            a = emb[d];
        } else {
            a = 0.0f;
            for (int i = st; i < en; i++) {
                a += emb[(size_t)idr[i]*Dd + d];
            }
        }
        out[((size_t)b*Ss + s)*Dd + d] = a + pos[s*Dd + d];
    }
}

// ---------------- LayerNorm (+residual) -> fp32 out and split bf16 out ----------------
__global__ void ln_kernel(const float* __restrict__ in, const float* __restrict__ res,
                          float* __restrict__ out,
                          __nv_bfloat16* __restrict__ outh, __nv_bfloat16* __restrict__ outl,
                          const float* __restrict__ gamma, const float* __restrict__ beta)
{
    __shared__ float red[256];
    int row = blockIdx.x;
    const float* ip = in + (size_t)row*Dd;
    const float* rp = (res != nullptr) ? (res + (size_t)row*Dd) : nullptr;
    int t = threadIdx.x;
    float v0 = ip[t];
    float v1 = ip[t + 256];
    float v2 = ip[t + 512];
    if (rp != nullptr) {
        v0 += rp[t];
        v1 += rp[t + 256];
        v2 += rp[t + 512];
    }
    red[t] = v0 + v1 + v2;
    __syncthreads();
    for (int o = 128; o > 0; o >>= 1) {
        if (t < o) red[t] += red[t + o];
        __syncthreads();
    }
    float mean = red[0] * (1.0f / Dd);
    __syncthreads();
    float d0 = v0 - mean;
    float d1 = v1 - mean;
    float d2 = v2 - mean;
    red[t] = d0*d0 + d1*d1 + d2*d2;
    __syncthreads();
    for (int o = 128; o > 0; o >>= 1) {
        if (t < o) red[t] += red[t + o];
        __syncthreads();
    }
    float inv = rsqrtf(red[0] * (1.0f / Dd) + 1e-12f);
    float r0 = d0*inv*gamma[t]       + beta[t];
    float r1 = d1*inv*gamma[t + 256] + beta[t + 256];
    float r2 = d2*inv*gamma[t + 512] + beta[t + 512];
    size_t base = (size_t)row*Dd;
    out[base + t]       = r0;
    out[base + t + 256] = r1;
    out[base + t + 512] = r2;
    __nv_bfloat16 h, l;
    split_bf16(r0, &h, &l);
    outh[base + t] = h;
    outl[base + t] = l;
    split_bf16(r1, &h, &l);
    outh[base + t + 256] = h;
    outl[base + t + 256] = l;
    split_bf16(r2, &h, &l);
    outh[base + t + 512] = h;
    outl[base + t + 512] = l;
}

// ---------------- bf16x3 GEMM on pre-split inputs, register-staged pipeline ----------------
// C[M,N] = act(A @ B + bias); A=[M,K] split bf16 (Ah,Al), B=[K,N] split bf16 (Bh,Bl).
// acc = Ah*Bh + Ah*Bl + Al*Bh (fp32). 128x128 block tile, k-tile 32, 256 threads.
// Tile k+1 gmem loads are staged in registers during tile k's MMA section.
// act==0: write fp32 C.  act==1: exact GELU, write split bf16 Ch/Cl.

#define ASTRIDE 40
#define BSTRIDE 136

__global__ __launch_bounds__(256, 2)
void gemm_bs(const __nv_bfloat16* __restrict__ Ah, const __nv_bfloat16* __restrict__ Al,
             const __nv_bfloat16* __restrict__ Bh, const __nv_bfloat16* __restrict__ Bl,
             const float* __restrict__ bias, float* __restrict__ C,
             __nv_bfloat16* __restrict__ Ch, __nv_bfloat16* __restrict__ Cl,
             int M, int N, int K, int act)
{
    __shared__ __align__(16) __nv_bfloat16 Ash[128*ASTRIDE];
    __shared__ __align__(16) __nv_bfloat16 Asl[128*ASTRIDE];
    __shared__ __align__(16) __nv_bfloat16 Bsh[32*BSTRIDE];
    __shared__ __align__(16) __nv_bfloat16 Bsl[32*BSTRIDE];

    const int t    = threadIdx.x;
    const int lane = t & 31;
    const int warp = t >> 5;
    const int wm   = warp >> 1;
    const int wn   = warp & 1;
    const int bm   = blockIdx.y * 128;
    const int bn   = blockIdx.x * 128;
    const int lm   = lane & 15;
    const int lqq  = lane >> 4;

    // per-thread gmem slot indices (fixed across tiles)
    const int ar0 = t >> 2;
    const int akc = t & 3;
    const int ar1 = (t + 256) >> 2;
    const int br0 = t >> 4;
    const int bnc = t & 15;
    const int br1 = (t + 256) >> 4;

    float acc[2][8][4];
    for (int i = 0; i < 2; i++) {
        for (int j = 0; j < 8; j++) {
            for (int e = 0; e < 4; e++) {
                acc[i][j][e] = 0.0f;
            }
        }
    }

    const uint32_t aHi = (uint32_t)__cvta_generic_to_shared(Ash);
    const uint32_t aLo = (uint32_t)__cvta_generic_to_shared(Asl);
    const uint32_t bHi = (uint32_t)__cvta_generic_to_shared(Bsh);
    const uint32_t bLo = (uint32_t)__cvta_generic_to_shared(Bsl);

    uint4 pah0, pah1, pal0, pal1;
    uint4 pbh0, pbh1, pbl0, pbl1;

    // prefetch tile 0
    {
        size_t goA0 = (size_t)(bm + ar0)*K + akc*8;
        size_t goA1 = (size_t)(bm + ar1)*K + akc*8;
        size_t goB0 = (size_t)br0*N + bn + bnc*8;
        size_t goB1 = (size_t)br1*N + bn + bnc*8;
        pah0 = *(const uint4*)(Ah + goA0);
        pal0 = *(const uint4*)(Al + goA0);
        pah1 = *(const uint4*)(Ah + goA1);
        pal1 = *(const uint4*)(Al + goA1);
        pbh0 = *(const uint4*)(Bh + goB0);
        pbl0 = *(const uint4*)(Bl + goB0);
        pbh1 = *(const uint4*)(Bh + goB1);
        pbl1 = *(const uint4*)(Bl + goB1);
    }

    const int KT = K / 32;
    for (int kt = 0; kt < KT; kt++) {
        // store staged tile to smem
        *(uint4*)(&Ash[ar0*ASTRIDE + akc*8]) = pah0;
        *(uint4*)(&Asl[ar0*ASTRIDE + akc*8]) = pal0;
        *(uint4*)(&Ash[ar1*ASTRIDE + akc*8]) = pah1;
        *(uint4*)(&Asl[ar1*ASTRIDE + akc*8]) = pal1;
        *(uint4*)(&Bsh[br0*BSTRIDE + bnc*8]) = pbh0;
        *(uint4*)(&Bsl[br0*BSTRIDE + bnc*8]) = pbl0;
        *(uint4*)(&Bsh[br1*BSTRIDE + bnc*8]) = pbh1;
        *(uint4*)(&Bsl[br1*BSTRIDE + bnc*8]) = pbl1;
        __syncthreads();

        // stage next tile (LDG latency overlaps MMA below)
        if (kt + 1 < KT) {
            int k0 = (kt + 1) * 32;
            size_t goA0 = (size_t)(bm + ar0)*K + k0 + akc*8;
            size_t goA1 = (size_t)(bm + ar1)*K + k0 + akc*8;
            size_t goB0 = (size_t)(k0 + br0)*N + bn + bnc*8;
            size_t goB1 = (size_t)(k0 + br1)*N + bn + bnc*8;
            pah0 = *(const uint4*)(Ah + goA0);
            pal0 = *(const uint4*)(Al + goA0);
            pah1 = *(const uint4*)(Ah + goA1);
            pal1 = *(const uint4*)(Al + goA1);
            pbh0 = *(const uint4*)(Bh + goB0);
            pbl0 = *(const uint4*)(Bl + goB0);
            pbh1 = *(const uint4*)(Bh + goB1);
            pbl1 = *(const uint4*)(Bl + goB1);
        }

#pragma unroll
        for (int ks = 0; ks < 32; ks += 16) {
            uint32_t ahf[2][4];
            uint32_t alf[2][4];
#pragma unroll
            for (int i = 0; i < 2; i++) {
                uint32_t off = (uint32_t)(((wm*32 + i*16 + lm)*ASTRIDE + ks + lqq*8) * 2);
                ldsm4(ahf[i], aHi + off);
                ldsm4(alf[i], aLo + off);
            }
#pragma unroll
            for (int np = 0; np < 4; np++) {
                uint32_t bhf[4];
                uint32_t blf[4];
                uint32_t off = (uint32_t)(((ks + lm)*BSTRIDE + wn*64 + np*16 + lqq*8) * 2);
                ldsm4t(bhf, bHi + off);
                ldsm4t(blf, bLo + off);
#pragma unroll
                for (int i = 0; i < 2; i++) {
#pragma unroll
                    for (int jj = 0; jj < 2; jj++) {
                        int j = np*2 + jj;
                        mma16816(acc[i][j], ahf[i], bhf + jj*2);
                        mma16816(acc[i][j], ahf[i], blf + jj*2);
                        mma16816(acc[i][j], alf[i], bhf + jj*2);
                    }
                }
            }
        }
        __syncthreads();
    }

    const int tr = lane >> 2;
    const int tc = (lane & 3) * 2;
#pragma unroll
    for (int i = 0; i < 2; i++) {
#pragma unroll
        for (int j = 0; j < 8; j++) {
#pragma unroll
            for (int hh = 0; hh < 2; hh++) {
                int gr = bm + wm*32 + i*16 + tr + hh*8;
                int gc = bn + wn*64 + j*8 + tc;
                float u0 = acc[i][j][hh*2 + 0] + bias[gc];
                float u1 = acc[i][j][hh*2 + 1] + bias[gc + 1];
                if (act == 1) {
                    u0 = 0.5f*u0*(1.0f + erff(u0*0.70710678118654752f));
                    u1 = 0.5f*u1*(1.0f + erff(u1*0.70710678118654752f));
                    uint32_t hu, lu;
                    pack_split(u0, u1, &hu, &lu);
                    *(uint32_t*)(Ch + (size_t)gr*N + gc) = hu;
                    *(uint32_t*)(Cl + (size_t)gr*N + gc) = lu;
                } else {
                    float2 o2;
                    o2.x = u0;
                    o2.y = u1;
                    *(float2*)(C + (size_t)gr*N + gc) = o2;
                }
            }
        }
    }
}

// ---------------- fused flash attention (bf16x3 split MMA, online softmax) ----------------
// q/k/v live in one [NROWS, 2304] buffer (row stride QKVN).

#define QS 72

__global__ __launch_bounds__(256, 1)
void flash_attn(const float* __restrict__ qg, const float* __restrict__ kg,
                const float* __restrict__ vg, const int* __restrict__ mask,
                __nv_bfloat16* __restrict__ ctxh, __nv_bfloat16* __restrict__ ctxl)
{
    __shared__ __align__(16) __nv_bfloat16 sm[256*QS];
    __shared__ float smask[64];

    const int t    = threadIdx.x;
    const int lane = t & 31;
    const int w    = t >> 5;
    const int qt   = blockIdx.x;
    const int z    = blockIdx.y;
    const int b    = z / Hh;
    const int h    = z % Hh;

    const int lm = lane & 15;
    const int lq = lane >> 4;
    const int tr = lane >> 2;
    const int tc = (lane & 3) * 2;

    __nv_bfloat16* Qh = sm;
    __nv_bfloat16* Ql = sm + 128*QS;
    __nv_bfloat16* Kh = sm;
    __nv_bfloat16* Kl = sm + 64*QS;
    __nv_bfloat16* Vh = sm + 128*QS;
    __nv_bfloat16* Vl = sm + 192*QS;

    {
        const float* qp = qg + (size_t)(b*Ss + qt*128)*QKVN + h*HD;
#pragma unroll
        for (int i = 0; i < 8; i++) {
            int f  = t + i*256;
            int r  = f >> 4;
            int c4 = f & 15;
            float4 a4 = *(const float4*)(qp + (size_t)r*QKVN + c4*4);
            BF16x4 hv, lv;
            split_bf16(a4.x, &hv.b[0], &lv.b[0]);
            split_bf16(a4.y, &hv.b[1], &lv.b[1]);
            split_bf16(a4.z, &hv.b[2], &lv.b[2]);
            split_bf16(a4.w, &hv.b[3], &lv.b[3]);
            *(uint2*)(Qh + r*QS + c4*4) = hv.u;
            *(uint2*)(Ql + r*QS + c4*4) = lv.u;
        }
    }
    __syncthreads();

    uint32_t qh[4][4];
    uint32_t ql[4][4];
    {
        uint32_t qbh = (uint32_t)__cvta_generic_to_shared(Qh);
        uint32_t qbl = (uint32_t)__cvta_generic_to_shared(Ql);
#pragma unroll
        for (int kt = 0; kt < 4; kt++) {
            uint32_t off = (uint32_t)(((w*16 + lm)*QS + kt*16 + lq*8) * 2);
            ldsm4(qh[kt], qbh + off);
            ldsm4(ql[kt], qbl + off);
        }
    }
    __syncthreads();

    float o[8][4];
#pragma unroll
    for (int j = 0; j < 8; j++) {
        o[j][0] = 0.0f; o[j][1] = 0.0f; o[j][2] = 0.0f; o[j][3] = 0.0f;
    }
    float m0 = -1e30f;
    float m1 = -1e30f;
    float l0 = 0.0f;
    float l1 = 0.0f;

    const uint32_t kbh = (uint32_t)__cvta_generic_to_shared(Kh);
    const uint32_t kbl = (uint32_t)__cvta_generic_to_shared(Kl);
    const uint32_t vbh = (uint32_t)__cvta_generic_to_shared(Vh);
    const uint32_t vbl = (uint32_t)__cvta_generic_to_shared(Vl);

    for (int kt8 = 0; kt8 < 8; kt8++) {
        {
            const float* kp = kg + (size_t)(b*Ss + kt8*64)*QKVN + h*HD;
            const float* vp = vg + (size_t)(b*Ss + kt8*64)*QKVN + h*HD;
#pragma unroll
            for (int i = 0; i < 4; i++) {
                int f  = t + i*256;
                int r  = f >> 4;
                int c4 = f & 15;
                float4 a4 = *(const float4*)(kp + (size_t)r*QKVN + c4*4);
                BF16x4 hv, lv;
                split_bf16(a4.x, &hv.b[0], &lv.b[0]);
                split_bf16(a4.y, &hv.b[1], &lv.b[1]);
                split_bf16(a4.z, &hv.b[2], &lv.b[2]);
                split_bf16(a4.w, &hv.b[3], &lv.b[3]);
                *(uint2*)(Kh + r*QS + c4*4) = hv.u;
                *(uint2*)(Kl + r*QS + c4*4) = lv.u;
                float4 b4 = *(const float4*)(vp + (size_t)r*QKVN + c4*4);
                split_bf16(b4.x, &hv.b[0], &lv.b[0]);
                split_bf16(b4.y, &hv.b[1], &lv.b[1]);
                split_bf16(b4.z, &hv.b[2], &lv.b[2]);
                split_bf16(b4.w, &hv.b[3], &lv.b[3]);
                *(uint2*)(Vh + r*QS + c4*4) = hv.u;
                *(uint2*)(Vl + r*QS + c4*4) = lv.u;
            }
        }
        if (t < 64) {
            smask[t] = (mask[b*Ss + kt8*64 + t] != 0) ? 0.0f : -1e9f;
        }
        __syncthreads();

        float s[8][4];
#pragma unroll
        for (int j = 0; j < 8; j++) {
            s[j][0] = 0.0f; s[j][1] = 0.0f; s[j][2] = 0.0f; s[j][3] = 0.0f;
        }
#pragma unroll
        for (int kt = 0; kt < 4; kt++) {
#pragma unroll
            for (int nt = 0; nt < 4; nt++) {
                uint32_t off = (uint32_t)(((nt*16 + lm)*QS + kt*16 + lq*8) * 2);
                uint32_t khf[4];
                uint32_t klf[4];
                ldsm4(khf, kbh + off);
                ldsm4(klf, kbl + off);
                uint32_t b0h[2] = {khf[0], khf[2]};
                uint32_t b1h[2] = {khf[1], khf[3]};
                uint32_t b0l[2] = {klf[0], klf[2]};
                uint32_t b1l[2] = {klf[1], klf[3]};
                mma16816(s[nt*2],     qh[kt], b0h);
                mma16816(s[nt*2],     qh[kt], b0l);
                mma16816(s[nt*2],     ql[kt], b0h);
                mma16816(s[nt*2 + 1], qh[kt], b1h);
                mma16816(s[nt*2 + 1], qh[kt], b1l);
                mma16816(s[nt*2 + 1], ql[kt], b1h);
            }
        }

        float mx0 = -1e30f;
        float mx1 = -1e30f;
#pragma unroll
        for (int j = 0; j < 8; j++) {
            float bi0 = smask[j*8 + tc];
            float bi1 = smask[j*8 + tc + 1];
            s[j][0] = s[j][0]*0.125f + bi0;
            s[j][1] = s[j][1]*0.125f + bi1;
            s[j][2] = s[j][2]*0.125f + bi0;
            s[j][3] = s[j][3]*0.125f + bi1;
            mx0 = fmaxf(mx0, fmaxf(s[j][0], s[j][1]));
            mx1 = fmaxf(mx1, fmaxf(s[j][2], s[j][3]));
        }
        mx0 = fmaxf(mx0, __shfl_xor_sync(0xffffffffu, mx0, 1));
        mx0 = fmaxf(mx0, __shfl_xor_sync(0xffffffffu, mx0, 2));
        mx1 = fmaxf(mx1, __shfl_xor_sync(0xffffffffu, mx1, 1));
        mx1 = fmaxf(mx1, __shfl_xor_sync(0xffffffffu, mx1, 2));
        float mn0 = fmaxf(m0, mx0);
        float mn1 = fmaxf(m1, mx1);
        float sc0 = __expf(m0 - mn0);
        float sc1 = __expf(m1 - mn1);
        m0 = mn0;
        m1 = mn1;
        float su0 = 0.0f;
        float su1 = 0.0f;
#pragma unroll
        for (int j = 0; j < 8; j++) {
            s[j][0] = __expf(s[j][0] - mn0);
            s[j][1] = __expf(s[j][1] - mn0);
            s[j][2] = __expf(s[j][2] - mn1);
            s[j][3] = __expf(s[j][3] - mn1);
            su0 += s[j][0] + s[j][1];
            su1 += s[j][2] + s[j][3];
            o[j][0] *= sc0;
            o[j][1] *= sc0;
            o[j][2] *= sc1;
            o[j][3] *= sc1;
        }
        su0 += __shfl_xor_sync(0xffffffffu, su0, 1);
        su0 += __shfl_xor_sync(0xffffffffu, su0, 2);
        su1 += __shfl_xor_sync(0xffffffffu, su1, 1);
        su1 += __shfl_xor_sync(0xffffffffu, su1, 2);
        l0 = l0*sc0 + su0;
        l1 = l1*sc1 + su1;

#pragma unroll
        for (int kt = 0; kt < 4; kt++) {
            uint32_t ph[4];
            uint32_t pl[4];
            pack_split(s[kt*2][0],     s[kt*2][1],     &ph[0], &pl[0]);
            pack_split(s[kt*2][2],     s[kt*2][3],     &ph[1], &pl[1]);
            pack_split(s[kt*2 + 1][0], s[kt*2 + 1][1], &ph[2], &pl[2]);
            pack_split(s[kt*2 + 1][2], s[kt*2 + 1][3], &ph[3], &pl[3]);
#pragma unroll
            for (int nt = 0; nt < 4; nt++) {
                uint32_t off = (uint32_t)(((kt*16 + lm)*QS + nt*16 + lq*8) * 2);
                uint32_t vhf[4];
                uint32_t vlf[4];
                ldsm4t(vhf, vbh + off);
                ldsm4t(vlf, vbl + off);
                mma16816(o[nt*2],     ph, vhf);
                mma16816(o[nt*2],     ph, vlf);
                mma16816(o[nt*2],     pl, vhf);
                mma16816(o[nt*2 + 1], ph, vhf + 2);
                mma16816(o[nt*2 + 1], ph, vlf + 2);
                mma16816(o[nt*2 + 1], pl, vhf + 2);
            }
        }
        __syncthreads();
    }

    float inv0 = 1.0f / l0;
    float inv1 = 1.0f / l1;
    int gr0 = qt*128 + w*16 + tr;
#pragma unroll
    for (int j = 0; j < 8; j++) {
        int gc = h*HD + j*8 + tc;
        size_t r0off = ((size_t)(b*Ss) + gr0)*Dd + gc;
        size_t r1off = ((size_t)(b*Ss) + gr0 + 8)*Dd + gc;
        uint32_t hu, lu;
        pack_split(o[j][0]*inv0, o[j][1]*inv0, &hu, &lu);
        *(uint32_t*)(ctxh + r0off) = hu;
        *(uint32_t*)(ctxl + r0off) = lu;
        pack_split(o[j][2]*inv1, o[j][3]*inv1, &hu, &lu);
        *(uint32_t*)(ctxh + r1off) = hu;
        *(uint32_t*)(ctxl + r1off) = lu;
    }
}

// ---------------- head: logits = relu(x[:,0] @ preW + preB) @ clsW + clsB ----------------
__global__ void head_kernel(const float* __restrict__ x, const float* __restrict__ preW,
                            const float* __restrict__ preB, const float* __restrict__ clsW,
                            const float* __restrict__ clsB, float* __restrict__ out)
{
    __shared__ float xr[Dd];
    __shared__ float pre[Dd];
    int b = blockIdx.x;
    int t = threadIdx.x;
    for (int d = t; d < Dd; d += 256) {
        xr[d] = x[((size_t)b*Ss)*Dd + d];
    }
    __syncthreads();
    for (int o = t; o < Dd; o += 256) {
        float a = preB[o];
        for (int kk = 0; kk < Dd; kk++) {
            a = fmaf(xr[kk], preW[(size_t)kk*Dd + o], a);
        }
        pre[o] = fmaxf(a, 0.0f);
    }
    __syncthreads();
    if (t < 3) {
        float a = clsB[t];
        for (int kk = 0; kk < Dd; kk++) {
            a = fmaf(pre[kk], clsW[kk*3 + t], a);
        }
        out[b*3 + t] = a;
    }
}

// ---------------- host launcher ----------------
extern "C" void kernel_launch(void* const* d_in, const int* in_sizes, int n_in,
                              void* d_out, int out_size)
{
    const int*   input_ids = (const int*)d_in[0];
    const int*   seg_ids   = (const int*)d_in[1];
    const int*   attn_mask = (const int*)d_in[2];
    const float* emb_table = (const float*)d_in[4];
    const float* pos_emb   = (const float*)d_in[5];
    const float* emb_ln_s  = (const float*)d_in[6];
    const float* emb_ln_b  = (const float*)d_in[7];
    const float* Wq   = (const float*)d_in[8];
    const float* bq   = (const float*)d_in[9];
    const float* Wk   = (const float*)d_in[10];
    const float* bk   = (const float*)d_in[11];
    const float* Wv   = (const float*)d_in[12];
    const float* bv   = (const float*)d_in[13];
    const float* Wo   = (const float*)d_in[14];
    const float* bo   = (const float*)d_in[15];
    const float* ln1s = (const float*)d_in[16];
    const float* ln1b = (const float*)d_in[17];
    const float* W1   = (const float*)d_in[18];
    const float* b1   = (const float*)d_in[19];
    const float* W2   = (const float*)d_in[20];
    const float* b2   = (const float*)d_in[21];
    const float* ln2s = (const float*)d_in[22];
    const float* ln2b = (const float*)d_in[23];
    const float* preW = (const float*)d_in[24];
    const float* preB = (const float*)d_in[25];
    const float* clsW = (const float*)d_in[26];
    const float* clsB = (const float*)d_in[27];
    float* logits = (float*)d_out;

    float* x;
    float* tmp;
    float* qkv;
    float* bqkv;
    __nv_bfloat16* wh;
    __nv_bfloat16* wl;
    __nv_bfloat16* xh;
    __nv_bfloat16* xl;
    __nv_bfloat16* ch;
    __nv_bfloat16* cl;
    __nv_bfloat16* fh;
    __nv_bfloat16* fl;
    cudaGetSymbolAddress((void**)&x,    g_x);
    cudaGetSymbolAddress((void**)&tmp,  g_tmp);
    cudaGetSymbolAddress((void**)&qkv,  g_qkv);
    cudaGetSymbolAddress((void**)&bqkv, g_bqkv);
    cudaGetSymbolAddress((void**)&wh,   g_wh);
    cudaGetSymbolAddress((void**)&wl,   g_wl);
    cudaGetSymbolAddress((void**)&xh,   g_xh);
    cudaGetSymbolAddress((void**)&xl,   g_xl);
    cudaGetSymbolAddress((void**)&ch,   g_ch);
    cudaGetSymbolAddress((void**)&cl,   g_cl);
    cudaGetSymbolAddress((void**)&fh,   g_fh);
    cudaGetSymbolAddress((void**)&fl,   g_fl);

    // one-time weight prep: packed QKV at [0, 3*SZP), Wo at 3*SZP, W1/W2 after
    {
        int n4p = SZP / 4;
        int n4f = SZF / 4;
        int nqkv = Ll*Dd*(QKVN/4);
        pack_qkv<<<(nqkv + 255)/256, 256>>>(Wq, Wk, Wv, wh, wl);
        concat_bias<<<(Ll*QKVN + 255)/256, 256>>>(bq, bk, bv, bqkv);
        split_kernel<<<(n4p + 255)/256, 256>>>(Wo, wh + 3*(size_t)SZP, wl + 3*(size_t)SZP, n4p);
        split_kernel<<<(n4f + 255)/256, 256>>>(W1, wh + 4*(size_t)SZP, wl + 4*(size_t)SZP, n4f);
        split_kernel<<<(n4f + 255)/256, 256>>>(W2, wh + 4*(size_t)SZP + SZF, wl + 4*(size_t)SZP + SZF, n4f);
    }

    merge_kernel<<<dim3(Ss, Bb), 128>>>(input_ids, seg_ids, emb_table, pos_emb, tmp);
    ln_kernel<<<NROWS, 256>>>(tmp, nullptr, x, xh, xl, emb_ln_s, emb_ln_b);

    dim3 gP(Dd/128, NROWS/128);
    dim3 gQKV(QKVN/128, NROWS/128);
    dim3 gF1(FF/128, NROWS/128);

    for (int l = 0; l < Ll; l++) {
        const __nv_bfloat16* wqkvh = wh + (size_t)l*Dd*QKVN;
        const __nv_bfloat16* wqkvl = wl + (size_t)l*Dd*QKVN;
        const __nv_bfloat16* woh = wh + 3*(size_t)SZP + (size_t)l*Dd*Dd;
        const __nv_bfloat16* wol = wl + 3*(size_t)SZP + (size_t)l*Dd*Dd;
        const __nv_bfloat16* w1h = wh + 4*(size_t)SZP + (size_t)l*Dd*FF;
        const __nv_bfloat16* w1l = wl + 4*(size_t)SZP + (size_t)l*Dd*FF;
        const __nv_bfloat16* w2h = wh + 4*(size_t)SZP + (size_t)SZF + (size_t)l*FF*Dd;
        const __nv_bfloat16* w2l = wl + 4*(size_t)SZP + (size_t)SZF + (size_t)l*FF*Dd;

        gemm_bs<<<gQKV, 256>>>(xh, xl, wqkvh, wqkvl, bqkv + l*QKVN, qkv,
                               nullptr, nullptr, NROWS, QKVN, Dd, 0);

        flash_attn<<<dim3(Ss/128, BH), 256>>>(qkv, qkv + Dd, qkv + 2*Dd, attn_mask, ch, cl);

        gemm_bs<<<gP, 256>>>(ch, cl, woh, wol, bo + l*Dd, tmp, nullptr, nullptr, NROWS, Dd, Dd, 0);
        ln_kernel<<<NROWS, 256>>>(x, tmp, x, xh, xl, ln1s + l*Dd, ln1b + l*Dd);

        gemm_bs<<<gF1, 256>>>(xh, xl, w1h, w1l, b1 + l*FF, nullptr, fh, fl, NROWS, FF, Dd, 1);
        gemm_bs<<<gP, 256>>>(fh, fl, w2h, w2l, b2 + l*Dd, tmp, nullptr, nullptr, NROWS, Dd, FF, 0);
        ln_kernel<<<NROWS, 256>>>(x, tmp, x, xh, xl, ln2s + l*Dd, ln2b + l*Dd);
    }

    head_kernel<<<Bb, 256>>>(x, preW, preB, clsW, clsB, logits);
}

// round 15
// speedup vs baseline: 1.1579x; 1.1579x over previous
#include <cuda_runtime.h>
#include <cuda_bf16.h>
#include <cstdint>
#include <math.h>

// Problem dims
#define Bb 16
#define Ss 512
#define Dd 768
#define Hh 12
#define FF 3072
#define Ll 6
#define HD 64
#define BH (Bb*Hh)
#define NROWS (Bb*Ss)
#define QKVN 2304

#define SZP (Ll*Dd*Dd)
#define SZF (Ll*Dd*FF)
#define WTOT (4*SZP + 2*SZF)

// ---------------- scratch (device globals; no runtime allocation) ----------------
__device__ float g_x   [NROWS*Dd];
__device__ float g_tmp [NROWS*Dd];
__device__ float g_qkv [(size_t)NROWS*QKVN];
__device__ float g_bqkv[Ll*QKVN];

__device__ __nv_bfloat16 g_wh[WTOT];
__device__ __nv_bfloat16 g_wl[WTOT];
__device__ __nv_bfloat16 g_xh[NROWS*Dd];
__device__ __nv_bfloat16 g_xl[NROWS*Dd];
__device__ __nv_bfloat16 g_ch[NROWS*Dd];
__device__ __nv_bfloat16 g_cl[NROWS*Dd];
__device__ __nv_bfloat16 g_fh[NROWS*FF];
__device__ __nv_bfloat16 g_fl[NROWS*FF];

// ---------------- common helpers ----------------
union BF16x4 {
    __nv_bfloat16 b[4];
    uint2 u;
};

__device__ __forceinline__ void ldsm4(uint32_t* r, uint32_t addr)
{
    asm volatile("ldmatrix.sync.aligned.m8n8.x4.shared.b16 {%0,%1,%2,%3}, [%4];"
        : "=r"(r[0]), "=r"(r[1]), "=r"(r[2]), "=r"(r[3]) : "r"(addr));
}

__device__ __forceinline__ void ldsm4t(uint32_t* r, uint32_t addr)
{
    asm volatile("ldmatrix.sync.aligned.m8n8.x4.trans.shared.b16 {%0,%1,%2,%3}, [%4];"
        : "=r"(r[0]), "=r"(r[1]), "=r"(r[2]), "=r"(r[3]) : "r"(addr));
}

__device__ __forceinline__ void mma16816(float* c, const uint32_t* a, const uint32_t* b)
{
    asm volatile("mma.sync.aligned.m16n8k16.row.col.f32.bf16.bf16.f32 "
        "{%0,%1,%2,%3}, {%4,%5,%6,%7}, {%8,%9}, {%0,%1,%2,%3};"
        : "+f"(c[0]), "+f"(c[1]), "+f"(c[2]), "+f"(c[3])
        : "r"(a[0]), "r"(a[1]), "r"(a[2]), "r"(a[3]), "r"(b[0]), "r"(b[1]));
}

__device__ __forceinline__ void split_bf16(float x, __nv_bfloat16* hi, __nv_bfloat16* lo)
{
    __nv_bfloat16 h = __float2bfloat16_rn(x);
    *hi = h;
    *lo = __float2bfloat16_rn(x - __bfloat162float(h));
}

__device__ __forceinline__ void pack_split(float x, float y, uint32_t* hp, uint32_t* lp)
{
    __nv_bfloat16 hx = __float2bfloat16_rn(x);
    __nv_bfloat16 hy = __float2bfloat16_rn(y);
    __nv_bfloat16 lx = __float2bfloat16_rn(x - __bfloat162float(hx));
    __nv_bfloat16 ly = __float2bfloat16_rn(y - __bfloat162float(hy));
    *hp = ((uint32_t)__bfloat16_as_ushort(hy) << 16) | (uint32_t)__bfloat16_as_ushort(hx);
    *lp = ((uint32_t)__bfloat16_as_ushort(ly) << 16) | (uint32_t)__bfloat16_as_ushort(lx);
}

// ---------------- split: fp32 -> bf16 hi/lo (elementwise, float4) ----------------
__global__ void split_kernel(const float* __restrict__ src, __nv_bfloat16* __restrict__ hi,
                             __nv_bfloat16* __restrict__ lo, int n4)
{
    int i = blockIdx.x*blockDim.x + threadIdx.x;
    if (i < n4) {
        float4 v = ((const float4*)src)[i];
        BF16x4 h, l;
        split_bf16(v.x, &h.b[0], &l.b[0]);
        split_bf16(v.y, &h.b[1], &l.b[1]);
        split_bf16(v.z, &h.b[2], &l.b[2]);
        split_bf16(v.w, &h.b[3], &l.b[3]);
        ((uint2*)hi)[i] = h.u;
        ((uint2*)lo)[i] = l.u;
    }
}

// ---------------- pack Wq/Wk/Wv into interleaved [Ll][Dd][2304] split bf16 ----------------
__global__ void pack_qkv(const float* __restrict__ Wq, const float* __restrict__ Wk,
                         const float* __restrict__ Wv,
                         __nv_bfloat16* __restrict__ hi, __nv_bfloat16* __restrict__ lo)
{
    int i = blockIdx.x*blockDim.x + threadIdx.x;   // over Ll*Dd*(QKVN/4)
    if (i < Ll*Dd*(QKVN/4)) {
        int c4 = i % (QKVN/4);
        int rl = i / (QKVN/4);                     // rl = l*Dd + r
        int c  = c4*4;
        int sel = c / Dd;
        int sc  = c % Dd;
        const float* src = (sel == 0) ? Wq : ((sel == 1) ? Wk : Wv);
        float4 v = *(const float4*)(src + (size_t)rl*Dd + sc);
        BF16x4 h, l;
        split_bf16(v.x, &h.b[0], &l.b[0]);
        split_bf16(v.y, &h.b[1], &l.b[1]);
        split_bf16(v.z, &h.b[2], &l.b[2]);
        split_bf16(v.w, &h.b[3], &l.b[3]);
        *(uint2*)(hi + (size_t)rl*QKVN + c) = h.u;
        *(uint2*)(lo + (size_t)rl*QKVN + c) = l.u;
    }
}

__global__ void concat_bias(const float* __restrict__ bq, const float* __restrict__ bk,
                            const float* __restrict__ bv, float* __restrict__ out)
{
    int i = blockIdx.x*blockDim.x + threadIdx.x;
    if (i < Ll*QKVN) {
        int l = i / QKVN;
        int c = i % QKVN;
        float v;
        if (c < Dd) {
            v = bq[l*Dd + c];
        } else if (c < 2*Dd) {
            v = bk[l*Dd + c - Dd];
        } else {
            v = bv[l*Dd + c - 2*Dd];
        }
        out[i] = v;
    }
}

// ---------------- embedding segment-merge + pos add ----------------
__global__ void merge_kernel(const int* __restrict__ ids, const int* __restrict__ seg,
                             const float* __restrict__ emb, const float* __restrict__ pos,
                             float* __restrict__ out)
{
    int s = blockIdx.x;
    int b = blockIdx.y;
    const int* sr = seg + b*Ss;
    int lo = 0;
    int hi = Ss;
    while (lo < hi) {
        int m = (lo + hi) >> 1;
        if (sr[m] < s) lo = m + 1; else hi = m;
    }
    int st = lo;
    lo = st;
    hi = Ss;
    while (lo < hi) {
        int m = (lo + hi) >> 1;
        if (sr[m] <= s) lo = m + 1; else hi = m;
    }
    int en = lo;
    const int* idr = ids + b*Ss;
    for (int d = threadIdx.x; d < Dd; d += blockDim.x) {
        float a;
        if (st == en) {
            a = emb[d];
        } else {
            a = 0.0f;
            for (int i = st; i < en; i++) {
                a += emb[(size_t)idr[i]*Dd + d];
            }
        }
        out[((size_t)b*Ss + s)*Dd + d] = a + pos[s*Dd + d];
    }
}

// ---------------- LayerNorm (+residual) -> fp32 out and split bf16 out ----------------
__global__ void ln_kernel(const float* __restrict__ in, const float* __restrict__ res,
                          float* __restrict__ out,
                          __nv_bfloat16* __restrict__ outh, __nv_bfloat16* __restrict__ outl,
                          const float* __restrict__ gamma, const float* __restrict__ beta)
{
    __shared__ float red[256];
    int row = blockIdx.x;
    const float* ip = in + (size_t)row*Dd;
    const float* rp = (res != nullptr) ? (res + (size_t)row*Dd) : nullptr;
    int t = threadIdx.x;
    float v0 = ip[t];
    float v1 = ip[t + 256];
    float v2 = ip[t + 512];
    if (rp != nullptr) {
        v0 += rp[t];
        v1 += rp[t + 256];
        v2 += rp[t + 512];
    }
    red[t] = v0 + v1 + v2;
    __syncthreads();
    for (int o = 128; o > 0; o >>= 1) {
        if (t < o) red[t] += red[t + o];
        __syncthreads();
    }
    float mean = red[0] * (1.0f / Dd);
    __syncthreads();
    float d0 = v0 - mean;
    float d1 = v1 - mean;
    float d2 = v2 - mean;
    red[t] = d0*d0 + d1*d1 + d2*d2;
    __syncthreads();
    for (int o = 128; o > 0; o >>= 1) {
        if (t < o) red[t] += red[t + o];
        __syncthreads();
    }
    float inv = rsqrtf(red[0] * (1.0f / Dd) + 1e-12f);
    float r0 = d0*inv*gamma[t]       + beta[t];
    float r1 = d1*inv*gamma[t + 256] + beta[t + 256];
    float r2 = d2*inv*gamma[t + 512] + beta[t + 512];
    size_t base = (size_t)row*Dd;
    out[base + t]       = r0;
    out[base + t + 256] = r1;
    out[base + t + 512] = r2;
    __nv_bfloat16 h, l;
    split_bf16(r0, &h, &l);
    outh[base + t] = h;
    outl[base + t] = l;
    split_bf16(r1, &h, &l);
    outh[base + t + 256] = h;
    outl[base + t + 256] = l;
    split_bf16(r2, &h, &l);
    outh[base + t + 512] = h;
    outl[base + t + 512] = l;
}

// ---------------- bf16x3 GEMM on pre-split inputs (static smem, sync loads) ----------------
// Exact R12-proven transport. C[M,N] = act(A @ B + bias).
// acc = Ah*Bh + Ah*Bl + Al*Bh (fp32). 128x128 block tile, k-tile 32, 256 threads.
// act==0: write fp32 C.  act==1: exact GELU, write split bf16 Ch/Cl.

#define ASTRIDE 40
#define BSTRIDE 136

__global__ __launch_bounds__(256, 2)
void gemm_bs(const __nv_bfloat16* __restrict__ Ah, const __nv_bfloat16* __restrict__ Al,
             const __nv_bfloat16* __restrict__ Bh, const __nv_bfloat16* __restrict__ Bl,
             const float* __restrict__ bias, float* __restrict__ C,
             __nv_bfloat16* __restrict__ Ch, __nv_bfloat16* __restrict__ Cl,
             int M, int N, int K, int act)
{
    __shared__ __align__(16) __nv_bfloat16 Ash[128*ASTRIDE];
    __shared__ __align__(16) __nv_bfloat16 Asl[128*ASTRIDE];
    __shared__ __align__(16) __nv_bfloat16 Bsh[32*BSTRIDE];
    __shared__ __align__(16) __nv_bfloat16 Bsl[32*BSTRIDE];

    const int t    = threadIdx.x;
    const int lane = t & 31;
    const int warp = t >> 5;
    const int wm   = warp >> 1;
    const int wn   = warp & 1;
    const int bm   = blockIdx.y * 128;
    const int bn   = blockIdx.x * 128;
    const int lm   = lane & 15;
    const int lqq  = lane >> 4;

    float acc[2][8][4];
    for (int i = 0; i < 2; i++) {
        for (int j = 0; j < 8; j++) {
            for (int e = 0; e < 4; e++) {
                acc[i][j][e] = 0.0f;
            }
        }
    }

    const uint32_t aHi = (uint32_t)__cvta_generic_to_shared(Ash);
    const uint32_t aLo = (uint32_t)__cvta_generic_to_shared(Asl);
    const uint32_t bHi = (uint32_t)__cvta_generic_to_shared(Bsh);
    const uint32_t bLo = (uint32_t)__cvta_generic_to_shared(Bsl);

    for (int k0 = 0; k0 < K; k0 += 32) {
        // A tile: 128 rows x 32 k, hi and lo, 16B chunks (8 bf16)
#pragma unroll
        for (int i = 0; i < 2; i++) {
            int f  = t + i*256;
            int r  = f >> 2;
            int kc = f & 3;
            size_t go = (size_t)(bm + r)*K + k0 + kc*8;
            *(uint4*)(&Ash[r*ASTRIDE + kc*8]) = *(const uint4*)(Ah + go);
            *(uint4*)(&Asl[r*ASTRIDE + kc*8]) = *(const uint4*)(Al + go);
        }
        // B tile: 32 k-rows x 128 n, hi and lo
#pragma unroll
        for (int i = 0; i < 2; i++) {
            int f  = t + i*256;
            int r  = f >> 4;
            int nc = f & 15;
            size_t go = (size_t)(k0 + r)*N + bn + nc*8;
            *(uint4*)(&Bsh[r*BSTRIDE + nc*8]) = *(const uint4*)(Bh + go);
            *(uint4*)(&Bsl[r*BSTRIDE + nc*8]) = *(const uint4*)(Bl + go);
        }
        __syncthreads();

#pragma unroll
        for (int ks = 0; ks < 32; ks += 16) {
            uint32_t ahf[2][4];
            uint32_t alf[2][4];
#pragma unroll
            for (int i = 0; i < 2; i++) {
                uint32_t off = (uint32_t)(((wm*32 + i*16 + lm)*ASTRIDE + ks + lqq*8) * 2);
                ldsm4(ahf[i], aHi + off);
                ldsm4(alf[i], aLo + off);
            }
#pragma unroll
            for (int np = 0; np < 4; np++) {
                uint32_t bhf[4];
                uint32_t blf[4];
                uint32_t off = (uint32_t)(((ks + lm)*BSTRIDE + wn*64 + np*16 + lqq*8) * 2);
                ldsm4t(bhf, bHi + off);
                ldsm4t(blf, bLo + off);
#pragma unroll
                for (int i = 0; i < 2; i++) {
#pragma unroll
                    for (int jj = 0; jj < 2; jj++) {
                        int j = np*2 + jj;
                        mma16816(acc[i][j], ahf[i], bhf + jj*2);
                        mma16816(acc[i][j], ahf[i], blf + jj*2);
                        mma16816(acc[i][j], alf[i], bhf + jj*2);
                    }
                }
            }
        }
        __syncthreads();
    }

    const int tr = lane >> 2;
    const int tc = (lane & 3) * 2;
#pragma unroll
    for (int i = 0; i < 2; i++) {
#pragma unroll
        for (int j = 0; j < 8; j++) {
#pragma unroll
            for (int hh = 0; hh < 2; hh++) {
                int gr = bm + wm*32 + i*16 + tr + hh*8;
                int gc = bn + wn*64 + j*8 + tc;
                float u0 = acc[i][j][hh*2 + 0] + bias[gc];
                float u1 = acc[i][j][hh*2 + 1] + bias[gc + 1];
                if (act == 1) {
                    u0 = 0.5f*u0*(1.0f + erff(u0*0.70710678118654752f));
                    u1 = 0.5f*u1*(1.0f + erff(u1*0.70710678118654752f));
                    uint32_t hu, lu;
                    pack_split(u0, u1, &hu, &lu);
                    *(uint32_t*)(Ch + (size_t)gr*N + gc) = hu;
                    *(uint32_t*)(Cl + (size_t)gr*N + gc) = lu;
                } else {
                    float2 o2;
                    o2.x = u0;
                    o2.y = u1;
                    *(float2*)(C + (size_t)gr*N + gc) = o2;
                }
            }
        }
    }
}

// ---------------- fused flash attention (bf16x3 split MMA, online softmax) ----------------
// q/k/v live in one [NROWS, 2304] buffer (row stride QKVN).

#define QS 72

__global__ __launch_bounds__(256, 1)
void flash_attn(const float* __restrict__ qg, const float* __restrict__ kg,
                const float* __restrict__ vg, const int* __restrict__ mask,
                __nv_bfloat16* __restrict__ ctxh, __nv_bfloat16* __restrict__ ctxl)
{
    __shared__ __align__(16) __nv_bfloat16 sm[256*QS];
    __shared__ float smask[64];

    const int t    = threadIdx.x;
    const int lane = t & 31;
    const int w    = t >> 5;
    const int qt   = blockIdx.x;
    const int z    = blockIdx.y;
    const int b    = z / Hh;
    const int h    = z % Hh;

    const int lm = lane & 15;
    const int lq = lane >> 4;
    const int tr = lane >> 2;
    const int tc = (lane & 3) * 2;

    __nv_bfloat16* Qh = sm;
    __nv_bfloat16* Ql = sm + 128*QS;
    __nv_bfloat16* Kh = sm;
    __nv_bfloat16* Kl = sm + 64*QS;
    __nv_bfloat16* Vh = sm + 128*QS;
    __nv_bfloat16* Vl = sm + 192*QS;

    {
        const float* qp = qg + (size_t)(b*Ss + qt*128)*QKVN + h*HD;
#pragma unroll
        for (int i = 0; i < 8; i++) {
            int f  = t + i*256;
            int r  = f >> 4;
            int c4 = f & 15;
            float4 a4 = *(const float4*)(qp + (size_t)r*QKVN + c4*4);
            BF16x4 hv, lv;
            split_bf16(a4.x, &hv.b[0], &lv.b[0]);
            split_bf16(a4.y, &hv.b[1], &lv.b[1]);
            split_bf16(a4.z, &hv.b[2], &lv.b[2]);
            split_bf16(a4.w, &hv.b[3], &lv.b[3]);
            *(uint2*)(Qh + r*QS + c4*4) = hv.u;
            *(uint2*)(Ql + r*QS + c4*4) = lv.u;
        }
    }
    __syncthreads();

    uint32_t qh[4][4];
    uint32_t ql[4][4];
    {
        uint32_t qbh = (uint32_t)__cvta_generic_to_shared(Qh);
        uint32_t qbl = (uint32_t)__cvta_generic_to_shared(Ql);
#pragma unroll
        for (int kt = 0; kt < 4; kt++) {
            uint32_t off = (uint32_t)(((w*16 + lm)*QS + kt*16 + lq*8) * 2);
            ldsm4(qh[kt], qbh + off);
            ldsm4(ql[kt], qbl + off);
        }
    }
    __syncthreads();

    float o[8][4];
#pragma unroll
    for (int j = 0; j < 8; j++) {
        o[j][0] = 0.0f; o[j][1] = 0.0f; o[j][2] = 0.0f; o[j][3] = 0.0f;
    }
    float m0 = -1e30f;
    float m1 = -1e30f;
    float l0 = 0.0f;
    float l1 = 0.0f;

    const uint32_t kbh = (uint32_t)__cvta_generic_to_shared(Kh);
    const uint32_t kbl = (uint32_t)__cvta_generic_to_shared(Kl);
    const uint32_t vbh = (uint32_t)__cvta_generic_to_shared(Vh);
    const uint32_t vbl = (uint32_t)__cvta_generic_to_shared(Vl);

    for (int kt8 = 0; kt8 < 8; kt8++) {
        {
            const float* kp = kg + (size_t)(b*Ss + kt8*64)*QKVN + h*HD;
            const float* vp = vg + (size_t)(b*Ss + kt8*64)*QKVN + h*HD;
#pragma unroll
            for (int i = 0; i < 4; i++) {
                int f  = t + i*256;
                int r  = f >> 4;
                int c4 = f & 15;
                float4 a4 = *(const float4*)(kp + (size_t)r*QKVN + c4*4);
                BF16x4 hv, lv;
                split_bf16(a4.x, &hv.b[0], &lv.b[0]);
                split_bf16(a4.y, &hv.b[1], &lv.b[1]);
                split_bf16(a4.z, &hv.b[2], &lv.b[2]);
                split_bf16(a4.w, &hv.b[3], &lv.b[3]);
                *(uint2*)(Kh + r*QS + c4*4) = hv.u;
                *(uint2*)(Kl + r*QS + c4*4) = lv.u;
                float4 b4 = *(const float4*)(vp + (size_t)r*QKVN + c4*4);
                split_bf16(b4.x, &hv.b[0], &lv.b[0]);
                split_bf16(b4.y, &hv.b[1], &lv.b[1]);
                split_bf16(b4.z, &hv.b[2], &lv.b[2]);
                split_bf16(b4.w, &hv.b[3], &lv.b[3]);
                *(uint2*)(Vh + r*QS + c4*4) = hv.u;
                *(uint2*)(Vl + r*QS + c4*4) = lv.u;
            }
        }
        if (t < 64) {
            smask[t] = (mask[b*Ss + kt8*64 + t] != 0) ? 0.0f : -1e9f;
        }
        __syncthreads();

        float s[8][4];
#pragma unroll
        for (int j = 0; j < 8; j++) {
            s[j][0] = 0.0f; s[j][1] = 0.0f; s[j][2] = 0.0f; s[j][3] = 0.0f;
        }
#pragma unroll
        for (int kt = 0; kt < 4; kt++) {
#pragma unroll
            for (int nt = 0; nt < 4; nt++) {
                uint32_t off = (uint32_t)(((nt*16 + lm)*QS + kt*16 + lq*8) * 2);
                uint32_t khf[4];
                uint32_t klf[4];
                ldsm4(khf, kbh + off);
                ldsm4(klf, kbl + off);
                uint32_t b0h[2] = {khf[0], khf[2]};
                uint32_t b1h[2] = {khf[1], khf[3]};
                uint32_t b0l[2] = {klf[0], klf[2]};
                uint32_t b1l[2] = {klf[1], klf[3]};
                mma16816(s[nt*2],     qh[kt], b0h);
                mma16816(s[nt*2],     qh[kt], b0l);
                mma16816(s[nt*2],     ql[kt], b0h);
                mma16816(s[nt*2 + 1], qh[kt], b1h);
                mma16816(s[nt*2 + 1], qh[kt], b1l);
                mma16816(s[nt*2 + 1], ql[kt], b1h);
            }
        }

        float mx0 = -1e30f;
        float mx1 = -1e30f;
#pragma unroll
        for (int j = 0; j < 8; j++) {
            float bi0 = smask[j*8 + tc];
            float bi1 = smask[j*8 + tc + 1];
            s[j][0] = s[j][0]*0.125f + bi0;
            s[j][1] = s[j][1]*0.125f + bi1;
            s[j][2] = s[j][2]*0.125f + bi0;
            s[j][3] = s[j][3]*0.125f + bi1;
            mx0 = fmaxf(mx0, fmaxf(s[j][0], s[j][1]));
            mx1 = fmaxf(mx1, fmaxf(s[j][2], s[j][3]));
        }
        mx0 = fmaxf(mx0, __shfl_xor_sync(0xffffffffu, mx0, 1));
        mx0 = fmaxf(mx0, __shfl_xor_sync(0xffffffffu, mx0, 2));
        mx1 = fmaxf(mx1, __shfl_xor_sync(0xffffffffu, mx1, 1));
        mx1 = fmaxf(mx1, __shfl_xor_sync(0xffffffffu, mx1, 2));
        float mn0 = fmaxf(m0, mx0);
        float mn1 = fmaxf(m1, mx1);
        float sc0 = __expf(m0 - mn0);
        float sc1 = __expf(m1 - mn1);
        m0 = mn0;
        m1 = mn1;
        float su0 = 0.0f;
        float su1 = 0.0f;
#pragma unroll
        for (int j = 0; j < 8; j++) {
            s[j][0] = __expf(s[j][0] - mn0);
            s[j][1] = __expf(s[j][1] - mn0);
            s[j][2] = __expf(s[j][2] - mn1);
            s[j][3] = __expf(s[j][3] - mn1);
            su0 += s[j][0] + s[j][1];
            su1 += s[j][2] + s[j][3];
            o[j][0] *= sc0;
            o[j][1] *= sc0;
            o[j][2] *= sc1;
            o[j][3] *= sc1;
        }
        su0 += __shfl_xor_sync(0xffffffffu, su0, 1);
        su0 += __shfl_xor_sync(0xffffffffu, su0, 2);
        su1 += __shfl_xor_sync(0xffffffffu, su1, 1);
        su1 += __shfl_xor_sync(0xffffffffu, su1, 2);
        l0 = l0*sc0 + su0;
        l1 = l1*sc1 + su1;

#pragma unroll
        for (int kt = 0; kt < 4; kt++) {
            uint32_t ph[4];
            uint32_t pl[4];
            pack_split(s[kt*2][0],     s[kt*2][1],     &ph[0], &pl[0]);
            pack_split(s[kt*2][2],     s[kt*2][3],     &ph[1], &pl[1]);
            pack_split(s[kt*2 + 1][0], s[kt*2 + 1][1], &ph[2], &pl[2]);
            pack_split(s[kt*2 + 1][2], s[kt*2 + 1][3], &ph[3], &pl[3]);
#pragma unroll
            for (int nt = 0; nt < 4; nt++) {
                uint32_t off = (uint32_t)(((kt*16 + lm)*QS + nt*16 + lq*8) * 2);
                uint32_t vhf[4];
                uint32_t vlf[4];
                ldsm4t(vhf, vbh + off);
                ldsm4t(vlf, vbl + off);
                mma16816(o[nt*2],     ph, vhf);
                mma16816(o[nt*2],     ph, vlf);
                mma16816(o[nt*2],     pl, vhf);
                mma16816(o[nt*2 + 1], ph, vhf + 2);
                mma16816(o[nt*2 + 1], ph, vlf + 2);
                mma16816(o[nt*2 + 1], pl, vhf + 2);
            }
        }
        __syncthreads();
    }

    float inv0 = 1.0f / l0;
    float inv1 = 1.0f / l1;
    int gr0 = qt*128 + w*16 + tr;
#pragma unroll
    for (int j = 0; j < 8; j++) {
        int gc = h*HD + j*8 + tc;
        size_t r0off = ((size_t)(b*Ss) + gr0)*Dd + gc;
        size_t r1off = ((size_t)(b*Ss) + gr0 + 8)*Dd + gc;
        uint32_t hu, lu;
        pack_split(o[j][0]*inv0, o[j][1]*inv0, &hu, &lu);
        *(uint32_t*)(ctxh + r0off) = hu;
        *(uint32_t*)(ctxl + r0off) = lu;
        pack_split(o[j][2]*inv1, o[j][3]*inv1, &hu, &lu);
        *(uint32_t*)(ctxh + r1off) = hu;
        *(uint32_t*)(ctxl + r1off) = lu;
    }
}

// ---------------- head: logits = relu(x[:,0] @ preW + preB) @ clsW + clsB ----------------
__global__ void head_kernel(const float* __restrict__ x, const float* __restrict__ preW,
                            const float* __restrict__ preB, const float* __restrict__ clsW,
                            const float* __restrict__ clsB, float* __restrict__ out)
{
    __shared__ float xr[Dd];
    __shared__ float pre[Dd];
    int b = blockIdx.x;
    int t = threadIdx.x;
    for (int d = t; d < Dd; d += 256) {
        xr[d] = x[((size_t)b*Ss)*Dd + d];
    }
    __syncthreads();
    for (int o = t; o < Dd; o += 256) {
        float a = preB[o];
        for (int kk = 0; kk < Dd; kk++) {
            a = fmaf(xr[kk], preW[(size_t)kk*Dd + o], a);
        }
        pre[o] = fmaxf(a, 0.0f);
    }
    __syncthreads();
    if (t < 3) {
        float a = clsB[t];
        for (int kk = 0; kk < Dd; kk++) {
            a = fmaf(pre[kk], clsW[kk*3 + t], a);
        }
        out[b*3 + t] = a;
    }
}

// ---------------- host launcher ----------------
extern "C" void kernel_launch(void* const* d_in, const int* in_sizes, int n_in,
                              void* d_out, int out_size)
{
    const int*   input_ids = (const int*)d_in[0];
    const int*   seg_ids   = (const int*)d_in[1];
    const int*   attn_mask = (const int*)d_in[2];
    const float* emb_table = (const float*)d_in[4];
    const float* pos_emb   = (const float*)d_in[5];
    const float* emb_ln_s  = (const float*)d_in[6];
    const float* emb_ln_b  = (const float*)d_in[7];
    const float* Wq   = (const float*)d_in[8];
    const float* bq   = (const float*)d_in[9];
    const float* Wk   = (const float*)d_in[10];
    const float* bk   = (const float*)d_in[11];
    const float* Wv   = (const float*)d_in[12];
    const float* bv   = (const float*)d_in[13];
    const float* Wo   = (const float*)d_in[14];
    const float* bo   = (const float*)d_in[15];
    const float* ln1s = (const float*)d_in[16];
    const float* ln1b = (const float*)d_in[17];
    const float* W1   = (const float*)d_in[18];
    const float* b1   = (const float*)d_in[19];
    const float* W2   = (const float*)d_in[20];
    const float* b2   = (const float*)d_in[21];
    const float* ln2s = (const float*)d_in[22];
    const float* ln2b = (const float*)d_in[23];
    const float* preW = (const float*)d_in[24];
    const float* preB = (const float*)d_in[25];
    const float* clsW = (const float*)d_in[26];
    const float* clsB = (const float*)d_in[27];
    float* logits = (float*)d_out;

    float* x;
    float* tmp;
    float* qkv;
    float* bqkv;
    __nv_bfloat16* wh;
    __nv_bfloat16* wl;
    __nv_bfloat16* xh;
    __nv_bfloat16* xl;
    __nv_bfloat16* ch;
    __nv_bfloat16* cl;
    __nv_bfloat16* fh;
    __nv_bfloat16* fl;
    cudaGetSymbolAddress((void**)&x,    g_x);
    cudaGetSymbolAddress((void**)&tmp,  g_tmp);
    cudaGetSymbolAddress((void**)&qkv,  g_qkv);
    cudaGetSymbolAddress((void**)&bqkv, g_bqkv);
    cudaGetSymbolAddress((void**)&wh,   g_wh);
    cudaGetSymbolAddress((void**)&wl,   g_wl);
    cudaGetSymbolAddress((void**)&xh,   g_xh);
    cudaGetSymbolAddress((void**)&xl,   g_xl);
    cudaGetSymbolAddress((void**)&ch,   g_ch);
    cudaGetSymbolAddress((void**)&cl,   g_cl);
    cudaGetSymbolAddress((void**)&fh,   g_fh);
    cudaGetSymbolAddress((void**)&fl,   g_fl);

    // one-time weight prep: packed QKV at [0, 3*SZP), Wo at 3*SZP, W1/W2 after
    {
        int n4p = SZP / 4;
        int n4f = SZF / 4;
        int nqkv = Ll*Dd*(QKVN/4);
        pack_qkv<<<(nqkv + 255)/256, 256>>>(Wq, Wk, Wv, wh, wl);
        concat_bias<<<(Ll*QKVN + 255)/256, 256>>>(bq, bk, bv, bqkv);
        split_kernel<<<(n4p + 255)/256, 256>>>(Wo, wh + 3*(size_t)SZP, wl + 3*(size_t)SZP, n4p);
        split_kernel<<<(n4f + 255)/256, 256>>>(W1, wh + 4*(size_t)SZP, wl + 4*(size_t)SZP, n4f);
        split_kernel<<<(n4f + 255)/256, 256>>>(W2, wh + 4*(size_t)SZP + SZF, wl + 4*(size_t)SZP + SZF, n4f);
    }

    merge_kernel<<<dim3(Ss, Bb), 128>>>(input_ids, seg_ids, emb_table, pos_emb, tmp);
    ln_kernel<<<NROWS, 256>>>(tmp, nullptr, x, xh, xl, emb_ln_s, emb_ln_b);

    dim3 gP(Dd/128, NROWS/128);
    dim3 gQKV(QKVN/128, NROWS/128);
    dim3 gF1(FF/128, NROWS/128);

    for (int l = 0; l < Ll; l++) {
        const __nv_bfloat16* wqkvh = wh + (size_t)l*Dd*QKVN;
        const __nv_bfloat16* wqkvl = wl + (size_t)l*Dd*QKVN;
        const __nv_bfloat16* woh = wh + 3*(size_t)SZP + (size_t)l*Dd*Dd;
        const __nv_bfloat16* wol = wl + 3*(size_t)SZP + (size_t)l*Dd*Dd;
        const __nv_bfloat16* w1h = wh + 4*(size_t)SZP + (size_t)l*Dd*FF;
        const __nv_bfloat16* w1l = wl + 4*(size_t)SZP + (size_t)l*Dd*FF;
        const __nv_bfloat16* w2h = wh + 4*(size_t)SZP + (size_t)SZF + (size_t)l*FF*Dd;
        const __nv_bfloat16* w2l = wl + 4*(size_t)SZP + (size_t)SZF + (size_t)l*FF*Dd;

        gemm_bs<<<gQKV, 256>>>(xh, xl, wqkvh, wqkvl, bqkv + l*QKVN, qkv,
                               nullptr, nullptr, NROWS, QKVN, Dd, 0);

        flash_attn<<<dim3(Ss/128, BH), 256>>>(qkv, qkv + Dd, qkv + 2*Dd, attn_mask, ch, cl);

        gemm_bs<<<gP, 256>>>(ch, cl, woh, wol, bo + l*Dd, tmp, nullptr, nullptr, NROWS, Dd, Dd, 0);
        ln_kernel<<<NROWS, 256>>>(x, tmp, x, xh, xl, ln1s + l*Dd, ln1b + l*Dd);

        gemm_bs<<<gF1, 256>>>(xh, xl, w1h, w1l, b1 + l*FF, nullptr, fh, fl, NROWS, FF, Dd, 1);
        gemm_bs<<<gP, 256>>>(fh, fl, w2h, w2l, b2 + l*Dd, tmp, nullptr, nullptr, NROWS, Dd, FF, 0);
        ln_kernel<<<NROWS, 256>>>(x, tmp, x, xh, xl, ln2s + l*Dd, ln2b + l*Dd);
    }

    head_kernel<<<Bb, 256>>>(x, preW, preB, clsW, clsB, logits);
}